// round 7
// baseline (speedup 1.0000x reference)
#include <cuda_runtime.h>
#include <math.h>

#define BB 4
#define TT 2048
#define DD 1024
#define DK 128
#define RR (BB*TT)   // 8192

#define BKV 32
#define BPB 40              // flash blocks per batch (chunked schedule)
#define NSLOT (BB*BPB)      // 160 partial slots

// Scratch (device globals: allocation-free)
__device__ float g_Q[RR*DK];
__device__ float g_K[RR*DK];
__device__ float g_V[RR*DK];
__device__ float g_O[RR*DK];
__device__ float g_pO[(size_t)NSLOT*128*DK];   // partial O per chunk slot
__device__ float g_pml[NSLOT*128*2];           // partial (m,l) per row

__device__ __forceinline__ unsigned f2tf(float f) {
    unsigned u; asm("cvt.rna.tf32.f32 %0, %1;" : "=r"(u) : "f"(f)); return u;
}

__device__ __forceinline__ void mma_tf32(float c[4],
    unsigned a0, unsigned a1, unsigned a2, unsigned a3,
    unsigned b0, unsigned b1)
{
    asm volatile(
        "mma.sync.aligned.m16n8k8.row.col.f32.tf32.tf32.f32 "
        "{%0,%1,%2,%3}, {%4,%5,%6,%7}, {%8,%9}, {%0,%1,%2,%3};"
        : "+f"(c[0]), "+f"(c[1]), "+f"(c[2]), "+f"(c[3])
        : "r"(a0), "r"(a1), "r"(a2), "r"(a3), "r"(b0), "r"(b1));
}

// ---------------------------------------------------------------------------
// tf32 GEMM, double-buffered + register-prefetch pipeline.
// C[128x128 tile] = A[M,K] @ B[K,N], row-major fp32 in/out.
// 256 threads = 8 warps as 2(m) x 4(n); warp tile 64x32; BK=32.
// One __syncthreads per k-iter; LDG for iter i+1 overlaps compute of iter i.
// ---------------------------------------------------------------------------
#define GST 136

__device__ __forceinline__ void gemm128_tf32(
    const float* __restrict__ A, const float* __restrict__ Bw,
    float* __restrict__ C, int N, int K, int m0, int n0)
{
    __shared__ unsigned As[2 * 32 * GST];
    __shared__ unsigned Bs[2 * 32 * GST];

    const int tid = threadIdx.x, lane = tid & 31, w = tid >> 5;
    const int wm = (w >> 2) * 64, wn = (w & 3) * 32;
    const int g = lane >> 2, c = lane & 3;

    float acc[4][4][4];
#pragma unroll
    for (int mf = 0; mf < 4; mf++)
#pragma unroll
        for (int nf = 0; nf < 4; nf++)
#pragma unroll
            for (int j = 0; j < 4; j++) acc[mf][nf][j] = 0.f;

    const int arow = tid >> 1, acol = (tid & 1) * 16;   // A: 128 rows x 32 k
    const int brow = tid >> 3, bcol = (tid & 7) * 4;    // B: 32 k x 128 n

    // prefetch k0 = 0
    float4 av[4], bv[4];
#pragma unroll
    for (int i = 0; i < 4; i++) {
        av[i] = *(const float4*)&A[(size_t)(m0 + arow) * K + acol + i * 4];
        bv[i] = *(const float4*)&Bw[(size_t)brow * N + n0 + bcol + i * 32];
    }

    int s = 0;
    for (int k0 = 0; k0 < K; k0 += 32) {
        unsigned* Ab = As + s * 32 * GST;
        unsigned* Bb = Bs + s * 32 * GST;
        // stage (cvt to tf32)
#pragma unroll
        for (int i = 0; i < 4; i++) {
            int kk = acol + i * 4;
            Ab[(kk + 0) * GST + arow] = f2tf(av[i].x);
            Ab[(kk + 1) * GST + arow] = f2tf(av[i].y);
            Ab[(kk + 2) * GST + arow] = f2tf(av[i].z);
            Ab[(kk + 3) * GST + arow] = f2tf(av[i].w);
            uint4 u = {f2tf(bv[i].x), f2tf(bv[i].y), f2tf(bv[i].z), f2tf(bv[i].w)};
            *(uint4*)&Bb[brow * GST + bcol + i * 32] = u;
        }
        __syncthreads();

        // prefetch next k-slab (overlaps MMA below)
        if (k0 + 32 < K) {
#pragma unroll
            for (int i = 0; i < 4; i++) {
                av[i] = *(const float4*)&A[(size_t)(m0 + arow) * K + k0 + 32 + acol + i * 4];
                bv[i] = *(const float4*)&Bw[(size_t)(k0 + 32 + brow) * N + n0 + bcol + i * 32];
            }
        }

#pragma unroll
        for (int ks = 0; ks < 4; ks++) {
            const int kk = ks * 8 + c;
            unsigned a[4][4], b[4][2];
#pragma unroll
            for (int mf = 0; mf < 4; mf++) {
                int r = wm + mf * 16 + g;
                a[mf][0] = Ab[kk * GST + r];
                a[mf][1] = Ab[kk * GST + r + 8];
                a[mf][2] = Ab[(kk + 4) * GST + r];
                a[mf][3] = Ab[(kk + 4) * GST + r + 8];
            }
#pragma unroll
            for (int nf = 0; nf < 4; nf++) {
                int n = wn + nf * 8 + g;
                b[nf][0] = Bb[kk * GST + n];
                b[nf][1] = Bb[(kk + 4) * GST + n];
            }
#pragma unroll
            for (int mf = 0; mf < 4; mf++)
#pragma unroll
                for (int nf = 0; nf < 4; nf++)
                    mma_tf32(acc[mf][nf], a[mf][0], a[mf][1], a[mf][2], a[mf][3],
                             b[nf][0], b[nf][1]);
        }
        s ^= 1;
    }

    // epilogue
#pragma unroll
    for (int mf = 0; mf < 4; mf++)
#pragma unroll
        for (int nf = 0; nf < 4; nf++) {
            size_t r0 = (size_t)(m0 + wm + mf * 16 + g) * N + n0 + wn + nf * 8 + 2 * c;
            float2 lo = {acc[mf][nf][0], acc[mf][nf][1]};
            float2 hi = {acc[mf][nf][2], acc[mf][nf][3]};
            *(float2*)&C[r0]                 = lo;
            *(float2*)&C[r0 + (size_t)8 * N] = hi;
        }
}

__global__ __launch_bounds__(256) void qkv_kernel(
    const float* __restrict__ x, const float* __restrict__ Wq,
    const float* __restrict__ Wk, const float* __restrict__ Wv)
{
    const float* W; float* C;
    if (blockIdx.z == 0)      { W = Wq; C = g_Q; }
    else if (blockIdx.z == 1) { W = Wk; C = g_K; }
    else                      { W = Wv; C = g_V; }
    gemm128_tf32(x, W, C, DK, DD, blockIdx.x * 128, 0);
}

__global__ __launch_bounds__(256) void outproj_kernel(
    const float* __restrict__ Wo, float* __restrict__ out)
{
    gemm128_tf32(g_O, Wo, out, DD, DK, blockIdx.y * 128, blockIdx.x * 128);
}

// ---------------------------------------------------------------------------
// Flash attention, tf32 mma, split-KV, double-buffered KV pipeline.
// BQ=128, BKV=32, 256 threads = 8 warps; warp owns 16 q-rows.
// Chunk = up to 16 KV tiles; partial (O,m,l) -> g_pO/g_pml.
// K/V smem double-buffered; LDG of tile t+1 overlaps compute of tile t;
// ONE __syncthreads per tile.
// ---------------------------------------------------------------------------
#define QSS 132
#define KSS 132
#define VSS 136
#define PSS 36
#define OFF_K (128*QSS)
#define OFF_V (OFF_K + 2*BKV*KSS)
#define OFF_P (OFF_V + 2*BKV*VSS)
#define FLASH_SMEM ((OFF_P + 128*PSS) * 4)   // 154,624 bytes

__global__ __launch_bounds__(256) void flash_kernel()
{
    extern __shared__ unsigned sm[];
    unsigned* Qs = sm;
    unsigned* Ks = sm + OFF_K;
    unsigned* Vs = sm + OFF_V;
    unsigned* Ps = sm + OFF_P;

    const int tid = threadIdx.x, lane = tid & 31, w = tid >> 5;
    const int g = lane >> 2, c = lane & 3;
    const int wm = w * 16;

    // ---- schedule decode: reversed order puts big (qt) chunks first ----
    const int b  = blockIdx.x / BPB;
    const int wr = BPB - 1 - (blockIdx.x % BPB);
    int qt = 0, chunk = 0, prefix = 0;
    {
        int accn = 0;
        for (int q = 0; q < 16; q++) {
            int n = q / 4 + 1;                 // chunks for q-tile q (16 KV tiles each)
            if (wr < accn + n) { qt = q; chunk = wr - accn; prefix = accn; break; }
            accn += n;
        }
    }
    const int slot = b * BPB + prefix + chunk;
    const int q0 = qt * 128;
    const int it_total = 4 * qt + 4;           // BKV=32 tiles for this q-tile
    const int t0 = chunk * 16;
    const int tlen = (it_total - t0 < 16) ? (it_total - t0) : 16;

    const float* Qg = g_Q + ((size_t)b * TT + q0) * DK;
    const float* Kg = g_K + (size_t)b * TT * DK;
    const float* Vg = g_V + (size_t)b * TT * DK;

    // load Q tile (tf32)
#pragma unroll
    for (int i = 0; i < 16; i++) {
        int idx = i * 256 + tid, r = idx >> 5, c4 = idx & 31;
        float4 v = *(const float4*)&Qg[r * 128 + c4 * 4];
        uint4 u = {f2tf(v.x), f2tf(v.y), f2tf(v.z), f2tf(v.w)};
        *(uint4*)&Qs[r * QSS + c4 * 4] = u;
    }

    float mr0 = -1e30f, mr1 = -1e30f, l0 = 0.f, l1 = 0.f;
    float O[16][4];
#pragma unroll
    for (int nf = 0; nf < 16; nf++)
#pragma unroll
        for (int j = 0; j < 4; j++) O[nf][j] = 0.f;

    const float scale = 0.08838834764831845f;   // 1/sqrt(128)

    // prefetch first KV tile (32x128 each: 4 float4 per thread)
    float4 kr[4], vr[4];
    {
        const float* Kj = Kg + (size_t)t0 * BKV * DK;
        const float* Vj = Vg + (size_t)t0 * BKV * DK;
#pragma unroll
        for (int i = 0; i < 4; i++) {
            int idx = i * 256 + tid, r = idx >> 5, c4 = idx & 31;
            kr[i] = *(const float4*)&Kj[r * 128 + c4 * 4];
            vr[i] = *(const float4*)&Vj[r * 128 + c4 * 4];
        }
    }

    int s = 0;
    for (int ti = 0; ti < tlen; ti++) {
        const int t = t0 + ti;
        unsigned* Kb = Ks + s * BKV * KSS;
        unsigned* Vb = Vs + s * BKV * VSS;

        // stage current tile (cvt to tf32)
#pragma unroll
        for (int i = 0; i < 4; i++) {
            int idx = i * 256 + tid, r = idx >> 5, c4 = idx & 31;
            uint4 uk = {f2tf(kr[i].x), f2tf(kr[i].y), f2tf(kr[i].z), f2tf(kr[i].w)};
            *(uint4*)&Kb[r * KSS + c4 * 4] = uk;
            uint4 uv = {f2tf(vr[i].x), f2tf(vr[i].y), f2tf(vr[i].z), f2tf(vr[i].w)};
            *(uint4*)&Vb[r * VSS + c4 * 4] = uv;
        }
        __syncthreads();

        // prefetch next tile (overlaps all compute below)
        if (ti + 1 < tlen) {
            const float* Kj = Kg + (size_t)(t + 1) * BKV * DK;
            const float* Vj = Vg + (size_t)(t + 1) * BKV * DK;
#pragma unroll
            for (int i = 0; i < 4; i++) {
                int idx = i * 256 + tid, r = idx >> 5, c4 = idx & 31;
                kr[i] = *(const float4*)&Kj[r * 128 + c4 * 4];
                vr[i] = *(const float4*)&Vj[r * 128 + c4 * 4];
            }
        }

        // --- S = Q K^T : warp 16x32, 4 n-frags ---
        float sfr[4][4];
#pragma unroll
        for (int nf = 0; nf < 4; nf++)
#pragma unroll
            for (int j = 0; j < 4; j++) sfr[nf][j] = 0.f;

#pragma unroll
        for (int ks = 0; ks < 16; ks++) {
            const int kk = ks * 8 + c;
            unsigned a0 = Qs[(wm + g) * QSS + kk];
            unsigned a1 = Qs[(wm + g + 8) * QSS + kk];
            unsigned a2 = Qs[(wm + g) * QSS + kk + 4];
            unsigned a3 = Qs[(wm + g + 8) * QSS + kk + 4];
#pragma unroll
            for (int nf = 0; nf < 4; nf++) {
                int n = nf * 8 + g;
                mma_tf32(sfr[nf], a0, a1, a2, a3,
                         Kb[n * KSS + kk], Kb[n * KSS + kk + 4]);
            }
        }

        // scale + causal mask
#pragma unroll
        for (int nf = 0; nf < 4; nf++)
#pragma unroll
            for (int j = 0; j < 4; j++) sfr[nf][j] *= scale;

        if (t * BKV + BKV - 1 > q0 + wm) {
            const int r0g = q0 + wm + g, r1g = r0g + 8;
#pragma unroll
            for (int nf = 0; nf < 4; nf++) {
                int col = t * BKV + nf * 8 + 2 * c;
                if (col     > r0g) sfr[nf][0] = -1e30f;
                if (col + 1 > r0g) sfr[nf][1] = -1e30f;
                if (col     > r1g) sfr[nf][2] = -1e30f;
                if (col + 1 > r1g) sfr[nf][3] = -1e30f;
            }
        }

        // --- online softmax (rows wm+g, wm+g+8; reduce over 4-lane quad) ---
        float rm0 = -1e30f, rm1 = -1e30f;
#pragma unroll
        for (int nf = 0; nf < 4; nf++) {
            rm0 = fmaxf(rm0, fmaxf(sfr[nf][0], sfr[nf][1]));
            rm1 = fmaxf(rm1, fmaxf(sfr[nf][2], sfr[nf][3]));
        }
        rm0 = fmaxf(rm0, __shfl_xor_sync(0xffffffffu, rm0, 1));
        rm0 = fmaxf(rm0, __shfl_xor_sync(0xffffffffu, rm0, 2));
        rm1 = fmaxf(rm1, __shfl_xor_sync(0xffffffffu, rm1, 1));
        rm1 = fmaxf(rm1, __shfl_xor_sync(0xffffffffu, rm1, 2));

        float mn0 = fmaxf(mr0, rm0), mn1 = fmaxf(mr1, rm1);
        float al0 = __expf(mr0 - mn0), al1 = __expf(mr1 - mn1);
        float sum0 = 0.f, sum1 = 0.f;
#pragma unroll
        for (int nf = 0; nf < 4; nf++) {
            float p0 = __expf(sfr[nf][0] - mn0);
            float p1 = __expf(sfr[nf][1] - mn0);
            float p2 = __expf(sfr[nf][2] - mn1);
            float p3 = __expf(sfr[nf][3] - mn1);
            sum0 += p0 + p1; sum1 += p2 + p3;
            int col = nf * 8 + 2 * c;
            Ps[(wm + g) * PSS + col]         = f2tf(p0);
            Ps[(wm + g) * PSS + col + 1]     = f2tf(p1);
            Ps[(wm + g + 8) * PSS + col]     = f2tf(p2);
            Ps[(wm + g + 8) * PSS + col + 1] = f2tf(p3);
        }
        sum0 += __shfl_xor_sync(0xffffffffu, sum0, 1);
        sum0 += __shfl_xor_sync(0xffffffffu, sum0, 2);
        sum1 += __shfl_xor_sync(0xffffffffu, sum1, 1);
        sum1 += __shfl_xor_sync(0xffffffffu, sum1, 2);

        l0 = l0 * al0 + sum0; l1 = l1 * al1 + sum1;
        mr0 = mn0; mr1 = mn1;
#pragma unroll
        for (int nf = 0; nf < 16; nf++) {
            O[nf][0] *= al0; O[nf][1] *= al0;
            O[nf][2] *= al1; O[nf][3] *= al1;
        }
        __syncwarp();   // Ps rows are warp-private

        // --- O += P V : warp 16x128, 16 n-frags, 4 k-slices ---
#pragma unroll
        for (int ks = 0; ks < 4; ks++) {
            const int kk = ks * 8 + c;
            unsigned a0 = Ps[(wm + g) * PSS + kk];
            unsigned a1 = Ps[(wm + g + 8) * PSS + kk];
            unsigned a2 = Ps[(wm + g) * PSS + kk + 4];
            unsigned a3 = Ps[(wm + g + 8) * PSS + kk + 4];
#pragma unroll
            for (int nf = 0; nf < 16; nf++) {
                int n = nf * 8 + g;
                mma_tf32(O[nf], a0, a1, a2, a3,
                         Vb[kk * VSS + n], Vb[(kk + 4) * VSS + n]);
            }
        }
        s ^= 1;
    }

    // ---- write partial (unnormalized O, m, l) ----
    float* pO = g_pO + (size_t)slot * 128 * DK;
#pragma unroll
    for (int nf = 0; nf < 16; nf++) {
        int col = nf * 8 + 2 * c;
        float2 lo = {O[nf][0], O[nf][1]};
        float2 hi = {O[nf][2], O[nf][3]};
        *(float2*)&pO[(wm + g) * DK + col]     = lo;
        *(float2*)&pO[(wm + g + 8) * DK + col] = hi;
    }
    if (c == 0) {
        float* ml = g_pml + slot * 256;
        ml[(wm + g) * 2]         = mr0;
        ml[(wm + g) * 2 + 1]     = l0;
        ml[(wm + g + 8) * 2]     = mr1;
        ml[(wm + g + 8) * 2 + 1] = l1;
    }
}

// ---------------------------------------------------------------------------
// Combine partial chunks -> g_O (normalized). Grid 64 = (b,qt), 256 threads.
// ---------------------------------------------------------------------------
__global__ __launch_bounds__(256) void combine_kernel()
{
    const int b = blockIdx.x >> 4, qt = blockIdx.x & 15;
    const int nch = qt / 4 + 1;
    int prefix = 0;
    for (int q = 0; q < qt; q++) prefix += q / 4 + 1;
    const int base = b * BPB + prefix;

    const int row = threadIdx.x >> 1;
    const int ch0 = (threadIdx.x & 1) * 64;

    float mv[4], lv[4], wgt[4];
    float M = -1e30f;
    for (int i = 0; i < nch; i++) {
        mv[i] = g_pml[(base + i) * 256 + row * 2];
        lv[i] = g_pml[(base + i) * 256 + row * 2 + 1];
        M = fmaxf(M, mv[i]);
    }
    float L = 0.f;
    for (int i = 0; i < nch; i++) { wgt[i] = __expf(mv[i] - M); L += wgt[i] * lv[i]; }
    const float invL = 1.f / L;

    const size_t orow = ((size_t)b * TT + qt * 128 + row) * DK;
#pragma unroll 4
    for (int j = 0; j < 64; j += 4) {
        float4 a = {0.f, 0.f, 0.f, 0.f};
        for (int i = 0; i < nch; i++) {
            float4 v = *(const float4*)&g_pO[((size_t)(base + i) * 128 + row) * DK + ch0 + j];
            a.x += wgt[i] * v.x; a.y += wgt[i] * v.y;
            a.z += wgt[i] * v.z; a.w += wgt[i] * v.w;
        }
        a.x *= invL; a.y *= invL; a.z *= invL; a.w *= invL;
        *(float4*)&g_O[orow + ch0 + j] = a;
    }
}

// ---------------------------------------------------------------------------
extern "C" void kernel_launch(void* const* d_in, const int* in_sizes, int n_in,
                              void* d_out, int out_size)
{
    const float* x  = (const float*)d_in[0];
    const float* Wq = (const float*)d_in[1];
    const float* Wk = (const float*)d_in[2];
    const float* Wv = (const float*)d_in[3];
    const float* Wo = (const float*)d_in[4];
    float* out = (float*)d_out;

    cudaFuncSetAttribute(flash_kernel,
                         cudaFuncAttributeMaxDynamicSharedMemorySize, FLASH_SMEM);

    // QKV projections (tf32 tensor cores): [8192,1024] @ [1024,128] x3
    qkv_kernel<<<dim3(RR / 128, 1, 3), 256>>>(x, Wq, Wk, Wv);

    // Split-KV causal flash attention (tf32 tensor cores, pipelined)
    flash_kernel<<<NSLOT, 256, FLASH_SMEM>>>();

    // Merge partial softmax chunks
    combine_kernel<<<BB * 16, 256>>>();

    // Output projection: [8192,128] @ [128,1024]
    outproj_kernel<<<dim3(DD / 128, RR / 128), 256>>>(Wo, out);
}